// round 3
// baseline (speedup 1.0000x reference)
#include <cuda_runtime.h>

#define N_ATOMS 1024
#define NSHIFT 27
#define CUT2 25.0f                 // CUTOFF^2

#define ITILE 32                   // i-rows per block
#define JTILE 32                   // j-cols per block
#define BTHREADS 256
#define PAIRS_TILE (JTILE * NSHIFT)             // 864 pairs in tile
#define UNITS_PER_ROW (JTILE * NSHIFT * 3 / 4)  // 648 float4 units per i-row
#define ROW_STRIDE (N_ATOMS * 81u)              // floats per i-row of output

// Scratch (static device globals — no allocation).
__device__ float4 g_B[N_ATOMS * NSHIFT];    // B[j][s] = cart[j] + shift_cart[s]
__device__ float4 g_cart[N_ATOMS];          // cart[i]

// Kernel 1: build cart + B table. Negligible time.
__global__ void build_B(const float* __restrict__ frac,
                        const float* __restrict__ cell) {
    int t = blockIdx.x * blockDim.x + threadIdx.x;
    if (t >= N_ATOMS * NSHIFT) return;
    int j = t / NSHIFT;
    int s = t - j * NSHIFT;

    float c[9];
#pragma unroll
    for (int m = 0; m < 9; m++) c[m] = __ldg(cell + m);

    float f0 = __ldg(frac + 3 * j + 0);
    float f1 = __ldg(frac + 3 * j + 1);
    float f2 = __ldg(frac + 3 * j + 2);

    float sx = (float)(s / 9 - 1);
    float sy = (float)((s / 3) % 3 - 1);
    float sz = (float)(s % 3 - 1);

    float cart[3], sc[3];
#pragma unroll
    for (int k = 0; k < 3; k++) {
        cart[k] = fmaf(f2, c[6 + k], fmaf(f1, c[3 + k], f0 * c[k]));
        sc[k]   = fmaf(sz, c[6 + k], fmaf(sy, c[3 + k], sx * c[k]));
    }

    g_B[t] = make_float4(__fadd_rn(cart[0], sc[0]),
                         __fadd_rn(cart[1], sc[1]),
                         __fadd_rn(cart[2], sc[2]), 0.0f);
    if (s == 0) g_cart[j] = make_float4(cart[0], cart[1], cart[2], 0.0f);
}

// Kernel 2: coalesced float4 stores; outer loop over i-rows keeps c_i in
// registers (2 LDS per 16B stored instead of 3, no per-unit division).
__global__ void __launch_bounds__(BTHREADS)
radius_out(float* __restrict__ out) {
    __shared__ float4 shB[PAIRS_TILE];       // 13.5 KB
    __shared__ float4 shC[ITILE];

    const int i0 = blockIdx.x * ITILE;
    const int j0 = blockIdx.y * JTILE;
    const int tid = threadIdx.x;

    for (int t = tid; t < PAIRS_TILE; t += BTHREADS)
        shB[t] = g_B[j0 * NSHIFT + t];
    if (tid < ITILE)
        shC[tid] = g_cart[i0 + tid];
    __syncthreads();

    // base pointer of this block's first output row segment
    float* rowp = out + (unsigned)(i0 * N_ATOMS + j0) * 81u;

#pragma unroll 1
    for (int il = 0; il < ITILE; il++, rowp += ROW_STRIDE) {
        const float4 ci = shC[il];

#pragma unroll
        for (unsigned u = tid; u < UNITS_PER_ROW; u += BTHREADS) {
            unsigned off = u * 4u;          // float offset within row segment
            unsigned pl  = off / 3u;        // first pair (0..862)
            unsigned c0  = off - pl * 3u;   // phase (0..2)

            float4 bA = shB[pl];
            float4 bB = shB[pl + 1];

            // pair A
            float ax = __fadd_rn(bA.x, -ci.x);
            float ay = __fadd_rn(bA.y, -ci.y);
            float az = __fadd_rn(bA.z, -ci.z);
            float d2A = __fadd_rn(__fadd_rn(__fmul_rn(ax, ax), __fmul_rn(ay, ay)),
                                  __fmul_rn(az, az));
            bool kA = d2A < CUT2;
            float a0 = kA ? ax : 0.0f;
            float a1 = kA ? ay : 0.0f;
            float a2 = kA ? az : 0.0f;

            // pair B
            float bx = __fadd_rn(bB.x, -ci.x);
            float by = __fadd_rn(bB.y, -ci.y);
            float bz = __fadd_rn(bB.z, -ci.z);
            float d2B = __fadd_rn(__fadd_rn(__fmul_rn(bx, bx), __fmul_rn(by, by)),
                                  __fmul_rn(bz, bz));
            bool kB = d2B < CUT2;
            float a3 = kB ? bx : 0.0f;
            float a4 = kB ? by : 0.0f;
            float a5 = kB ? bz : 0.0f;

            // select window [c0, c0+4) out of {a0..a5}
            float o0 = (c0 == 0) ? a0 : ((c0 == 1) ? a1 : a2);
            float o1 = (c0 == 0) ? a1 : ((c0 == 1) ? a2 : a3);
            float o2 = (c0 == 0) ? a2 : ((c0 == 1) ? a3 : a4);
            float o3 = (c0 == 0) ? a3 : ((c0 == 1) ? a4 : a5);

            __stcs((float4*)(rowp + off), make_float4(o0, o1, o2, o3));
        }
    }
}

extern "C" void kernel_launch(void* const* d_in, const int* in_sizes, int n_in,
                              void* d_out, int out_size) {
    const float* frac = (const float*)d_in[0];   // [1024,3]
    const float* cell = (const float*)d_in[1];   // [3,3]
    float* out = (float*)d_out;                  // [1024,1024,27,3]

    build_B<<<(N_ATOMS * NSHIFT + 255) / 256, 256>>>(frac, cell);
    dim3 grid(N_ATOMS / ITILE, N_ATOMS / JTILE); // 32 x 32 = 1024 blocks
    radius_out<<<grid, BTHREADS>>>(out);
}

// round 4
// speedup vs baseline: 1.0774x; 1.0774x over previous
#include <cuda_runtime.h>
#include <cstdint>

#define N_ATOMS 1024
#define NSHIFT 27
#define CUT2 25.0f                    // CUTOFF^2

#define ITILE 32                      // i-rows per block
#define JTILE 16                      // j-cols per block
#define BTHREADS 256
#define PAIRS_TILE (JTILE * NSHIFT)   // 432 pairs per i-row
#define ROWS_PER_BUF 2
#define PAIRS_FILL (PAIRS_TILE * ROWS_PER_BUF)   // 864 pairs per fill
#define ROW_FLOATS (PAIRS_TILE * 3)   // 1296 floats = 5184 B per row segment
#define ROW_BYTES (ROW_FLOATS * 4)
#define NITER (ITILE / ROWS_PER_BUF)  // 16 fill/store iterations

// Scratch (static device globals — no allocation).
__device__ float4 g_B[N_ATOMS * NSHIFT];    // B[j][s] = cart[j] + shift_cart[s]
__device__ float4 g_cart[N_ATOMS];          // cart[i]

__device__ __forceinline__ uint32_t smem_u32(const void* p) {
    return (uint32_t)__cvta_generic_to_shared(p);
}

// Kernel 1: build cart + B table. Negligible time.
__global__ void build_B(const float* __restrict__ frac,
                        const float* __restrict__ cell) {
    int t = blockIdx.x * blockDim.x + threadIdx.x;
    if (t >= N_ATOMS * NSHIFT) return;
    int j = t / NSHIFT;
    int s = t - j * NSHIFT;

    float c[9];
#pragma unroll
    for (int m = 0; m < 9; m++) c[m] = __ldg(cell + m);

    float f0 = __ldg(frac + 3 * j + 0);
    float f1 = __ldg(frac + 3 * j + 1);
    float f2 = __ldg(frac + 3 * j + 2);

    float sx = (float)(s / 9 - 1);
    float sy = (float)((s / 3) % 3 - 1);
    float sz = (float)(s % 3 - 1);

    float cart[3], sc[3];
#pragma unroll
    for (int k = 0; k < 3; k++) {
        cart[k] = fmaf(f2, c[6 + k], fmaf(f1, c[3 + k], f0 * c[k]));
        sc[k]   = fmaf(sz, c[6 + k], fmaf(sy, c[3 + k], sx * c[k]));
    }

    g_B[t] = make_float4(__fadd_rn(cart[0], sc[0]),
                         __fadd_rn(cart[1], sc[1]),
                         __fadd_rn(cart[2], sc[2]), 0.0f);
    if (s == 0) g_cart[j] = make_float4(cart[0], cart[1], cart[2], 0.0f);
}

// Kernel 2: compute each pair once into an SMEM row buffer (conflict-free
// STS.32), then cp.async.bulk (TMA) stores the contiguous row segment to GMEM.
// Double-buffered: TMA write of rows k overlaps compute of rows k+2.
__global__ void __launch_bounds__(BTHREADS)
radius_out(float* __restrict__ out) {
    __shared__ float4 shB[PAIRS_TILE];                    // 6.75 KB
    __shared__ float4 shC[ITILE];                         // 0.5 KB
    __shared__ __align__(16) float buf[2][PAIRS_FILL * 3]; // 2 x 10368 B

    const int i0 = blockIdx.x * ITILE;
    const int j0 = blockIdx.y * JTILE;
    const int tid = threadIdx.x;

    for (int t = tid; t < PAIRS_TILE; t += BTHREADS)
        shB[t] = g_B[j0 * NSHIFT + t];
    if (tid < ITILE)
        shC[tid] = g_cart[i0 + tid];
    __syncthreads();

#pragma unroll 1
    for (int it = 0; it < NITER; it++) {
        const int b = it & 1;

        // Buffer b was handed to TMA at iteration it-2; make sure that bulk
        // group finished reading it before we overwrite.
        if (it >= 2) {
            if (tid == 0)
                asm volatile("cp.async.bulk.wait_group 1;" ::: "memory");
            __syncthreads();
        }

        // Fill: 864 pairs (2 i-rows x 432), one pair per thread-iteration.
#pragma unroll
        for (int pp = tid; pp < PAIRS_FILL; pp += BTHREADS) {
            int row = pp / PAIRS_TILE;              // 0 or 1
            int p   = pp - row * PAIRS_TILE;

            float4 bb = shB[p];
            float4 ci = shC[it * ROWS_PER_BUF + row];

            float dx = __fadd_rn(bb.x, -ci.x);
            float dy = __fadd_rn(bb.y, -ci.y);
            float dz = __fadd_rn(bb.z, -ci.z);
            float d2 = __fadd_rn(__fadd_rn(__fmul_rn(dx, dx), __fmul_rn(dy, dy)),
                                 __fmul_rn(dz, dz));
            bool keep = d2 < CUT2;   // self-edge yields disp==+0 anyway

            int o = pp * 3;
            buf[b][o + 0] = keep ? dx : 0.0f;
            buf[b][o + 1] = keep ? dy : 0.0f;
            buf[b][o + 2] = keep ? dz : 0.0f;
        }
        __syncthreads();

        if (tid == 0) {
            asm volatile("fence.proxy.async.shared::cta;" ::: "memory");
#pragma unroll
            for (int r = 0; r < ROWS_PER_BUF; r++) {
                int i = i0 + it * ROWS_PER_BUF + r;
                // row segment: out[(i*1024 + j0)*81 .. +1296), contiguous
                float* gdst = out + (size_t)((size_t)i * N_ATOMS + j0) * 81u;
                uint32_t ssrc = smem_u32(&buf[b][r * ROW_FLOATS]);
                asm volatile(
                    "cp.async.bulk.global.shared::cta.bulk_group [%0], [%1], %2;"
                    :: "l"(gdst), "r"(ssrc), "r"((uint32_t)ROW_BYTES)
                    : "memory");
            }
            asm volatile("cp.async.bulk.commit_group;" ::: "memory");
        }
    }

    // Drain all outstanding bulk stores before kernel exit.
    if (tid == 0)
        asm volatile("cp.async.bulk.wait_group 0;" ::: "memory");
}

extern "C" void kernel_launch(void* const* d_in, const int* in_sizes, int n_in,
                              void* d_out, int out_size) {
    const float* frac = (const float*)d_in[0];   // [1024,3]
    const float* cell = (const float*)d_in[1];   // [3,3]
    float* out = (float*)d_out;                  // [1024,1024,27,3]

    build_B<<<(N_ATOMS * NSHIFT + 255) / 256, 256>>>(frac, cell);
    dim3 grid(N_ATOMS / ITILE, N_ATOMS / JTILE); // (32, 64) = 2048 blocks
    radius_out<<<grid, BTHREADS>>>(out);
}